// round 1
// baseline (speedup 1.0000x reference)
#include <cuda_runtime.h>
#include <math.h>
#include <stdint.h>

// Problem constants
#define BQ   512   // batch
#define KT   64    // timesteps
#define EBD  256
#define VFD  512
#define H0   512
#define H1   256
#define H2   64
#define C0   1280  // 768 + 512
#define C1   768   // 512 + 256
#define C2   320   // 256 + 64

// ---------------- device scratch (static, no allocation) ----------------
// Interleaved combined weights: Wc[k][4*j + m], m in {ff1,ff2,ta,tb}, mask folded into ff1/ff2.
__device__ float Wc0[(size_t)C0 * 4 * H0];   // 10.5 MB
__device__ float Wc1[(size_t)C1 * 4 * H1];   // 3.1 MB
__device__ float Wc2[(size_t)C2 * 4 * H2];   // 0.33 MB
// Ping-pong hidden states
__device__ float h0b[2][BQ * H0];
__device__ float h1b[2][BQ * H1];
__device__ float h2b[2][BQ * H2];

// ---------------- weight prep: (hid,cat) row-major x4 -> (cat, 4*hid) interleaved ----------------
__global__ void prep_weights(const float* __restrict__ ff1, const float* __restrict__ ff2,
                             const float* __restrict__ ta,  const float* __restrict__ tb,
                             const float* __restrict__ mask,
                             float* __restrict__ dst, int hid, int cat)
{
    int idx = blockIdx.x * blockDim.x + threadIdx.x;
    if (idx >= hid * cat) return;
    int j = idx / cat;
    int k = idx - j * cat;
    float m = mask[idx];
    float* d = dst + (size_t)k * (4 * hid) + 4 * j;
    d[0] = ff1[idx] * m;
    d[1] = ff2[idx] * m;
    d[2] = ta[idx];
    d[3] = tb[idx];
}

// ---------------- fused CfC cell epilogue ----------------
__device__ __forceinline__ float cfc_out(float a0, float a1, float a2, float a3,
                                         float b0, float b1, float b2, float b3)
{
    float f1 = tanhf(a0 + b0);
    float f2 = tanhf(a1 + b1);
    float s  = (a2 + b2) + (a3 + b3);       // t_a * 1.0 + t_b
    float ti = 1.0f / (1.0f + expf(-s));    // sigmoid
    return f1 + ti * (f2 - f1);             // ff1*(1-ti) + ti*ff2
}

// ---------------- fused GEMM + CfC step ----------------
// Computes h_out[b][j] = CfC( x(b) . Wc[:,4j..4j+3] + bias ) where x(b) is the
// concatenation of up to 3 row segments (all segment boundaries are multiples of
// BK, so each K-tile lies entirely in one segment).
template<int BM, int BJ, int TM>
__global__ __launch_bounds__(256)
void cfc_step_kernel(const float* __restrict__ seg0, int st0, int len0,
                     const float* __restrict__ seg1, int st1, int len1,
                     const float* __restrict__ seg2, int st2,
                     const float* __restrict__ Wc,
                     const float* __restrict__ bff1, const float* __restrict__ bff2,
                     const float* __restrict__ bta,  const float* __restrict__ btb,
                     int cat, int hid, float* __restrict__ hout)
{
    constexpr int BK = 32;
    constexpr int TJ = BJ / 2;         // threads along j (each thread owns 2 j's: tx and tx+TJ)
    constexpr int TR = 256 / TJ;       // threads along rows
    static_assert(TR * TM == BM, "tile mismatch");

    __shared__ float  Xs[BM][BK + 1];
    __shared__ float4 Ws4[BK][BJ];     // Ws4[kk][j] = (ff1,ff2,ta,tb) weights for column jBase+j at k0+kk

    const int tid = threadIdx.x;
    const int tx  = tid % TJ;
    const int ty  = tid / TJ;
    const int rowBase = blockIdx.x * BM;
    const int jBase   = blockIdx.y * BJ;
    const int l01 = len0 + len1;

    float acc[TM][8];
    #pragma unroll
    for (int i = 0; i < TM; i++)
        #pragma unroll
        for (int q = 0; q < 8; q++) acc[i][q] = 0.0f;

    const float4* WcV = reinterpret_cast<const float4*>(Wc);  // row k has 'hid' float4s

    for (int k0 = 0; k0 < cat; k0 += BK) {
        // pick segment (uniform per tile: boundaries are multiples of BK)
        const float* sp; int ss, so;
        if (k0 < len0)      { sp = seg0; ss = st0; so = k0; }
        else if (k0 < l01)  { sp = seg1; ss = st1; so = k0 - len0; }
        else                { sp = seg2; ss = st2; so = k0 - l01; }

        // load X tile (BM x BK), coalesced along k
        #pragma unroll
        for (int l = tid; l < BM * BK; l += 256) {
            int r = l >> 5, c = l & 31;
            Xs[r][c] = sp[(size_t)(rowBase + r) * ss + so + c];
        }
        // load W tile (BK x BJ float4s), coalesced
        #pragma unroll
        for (int l = tid; l < BK * BJ; l += 256) {
            int kk = l / BJ, c4 = l % BJ;
            Ws4[kk][c4] = WcV[(size_t)(k0 + kk) * hid + jBase + c4];
        }
        __syncthreads();

        #pragma unroll
        for (int kk = 0; kk < BK; kk++) {
            float4 wa = Ws4[kk][tx];
            float4 wb = Ws4[kk][tx + TJ];
            #pragma unroll
            for (int i = 0; i < TM; i++) {
                float x = Xs[ty * TM + i][kk];
                acc[i][0] = fmaf(x, wa.x, acc[i][0]);
                acc[i][1] = fmaf(x, wa.y, acc[i][1]);
                acc[i][2] = fmaf(x, wa.z, acc[i][2]);
                acc[i][3] = fmaf(x, wa.w, acc[i][3]);
                acc[i][4] = fmaf(x, wb.x, acc[i][4]);
                acc[i][5] = fmaf(x, wb.y, acc[i][5]);
                acc[i][6] = fmaf(x, wb.z, acc[i][6]);
                acc[i][7] = fmaf(x, wb.w, acc[i][7]);
            }
        }
        __syncthreads();
    }

    const int j0 = jBase + tx;
    const int j1 = jBase + TJ + tx;
    const float b00 = bff1[j0], b01 = bff2[j0], b02 = bta[j0], b03 = btb[j0];
    const float b10 = bff1[j1], b11 = bff2[j1], b12 = bta[j1], b13 = btb[j1];

    #pragma unroll
    for (int i = 0; i < TM; i++) {
        int gr = rowBase + ty * TM + i;
        hout[(size_t)gr * hid + j0] = cfc_out(acc[i][0], acc[i][1], acc[i][2], acc[i][3], b00, b01, b02, b03);
        hout[(size_t)gr * hid + j1] = cfc_out(acc[i][4], acc[i][5], acc[i][6], acc[i][7], b10, b11, b12, b13);
    }
}

// ---------------- host launcher ----------------
extern "C" void kernel_launch(void* const* d_in, const int* in_sizes, int n_in,
                              void* d_out, int out_size)
{
    const float* base = (const float*)d_in[0];
    const float* vis  = (const float*)d_in[1];
    // per layer: 0 ff1_w, 1 ff1_b, 2 ff2_w, 3 ff2_b, 4 ta_w, 5 ta_b, 6 tb_w, 7 tb_b, 8 mask
    const float* w[3][9];
    for (int li = 0; li < 3; li++)
        for (int q = 0; q < 9; q++)
            w[li][q] = (const float*)d_in[2 + li * 9 + q];

    float *pWc0, *pWc1, *pWc2, *ph0, *ph1, *ph2;
    cudaGetSymbolAddress((void**)&pWc0, Wc0);
    cudaGetSymbolAddress((void**)&pWc1, Wc1);
    cudaGetSymbolAddress((void**)&pWc2, Wc2);
    cudaGetSymbolAddress((void**)&ph0, h0b);
    cudaGetSymbolAddress((void**)&ph1, h1b);
    cudaGetSymbolAddress((void**)&ph2, h2b);

    // zero initial hidden states (ping buffer 0)
    cudaMemsetAsync(ph0, 0, (size_t)BQ * H0 * sizeof(float));
    cudaMemsetAsync(ph1, 0, (size_t)BQ * H1 * sizeof(float));
    cudaMemsetAsync(ph2, 0, (size_t)BQ * H2 * sizeof(float));

    // fold masks + interleave weights
    prep_weights<<<(H0 * C0 + 255) / 256, 256>>>(w[0][0], w[0][2], w[0][4], w[0][6], w[0][8], pWc0, H0, C0);
    prep_weights<<<(H1 * C1 + 255) / 256, 256>>>(w[1][0], w[1][2], w[1][4], w[1][6], w[1][8], pWc1, H1, C1);
    prep_weights<<<(H2 * C2 + 255) / 256, 256>>>(w[2][0], w[2][2], w[2][4], w[2][6], w[2][8], pWc2, H2, C2);

    for (int t = 0; t < KT; t++) {
        int pi = t & 1, po = (t + 1) & 1;
        float* h0i = ph0 + (size_t)pi * BQ * H0;
        float* h0o = ph0 + (size_t)po * BQ * H0;
        float* h1i = ph1 + (size_t)pi * BQ * H1;
        float* h1o = ph1 + (size_t)po * BQ * H1;
        float* h2i = ph2 + (size_t)pi * BQ * H2;
        float* h2o = ph2 + (size_t)po * BQ * H2;

        // layer 0: x = [base_t(256) | vis_t(512) | h0(512)], hid 512
        cfc_step_kernel<64, 32, 4><<<dim3(BQ / 64, H0 / 32), 256>>>(
            base + (size_t)t * EBD, KT * EBD, EBD,
            vis  + (size_t)t * VFD, KT * VFD, VFD,
            h0i, H0,
            pWc0, w[0][1], w[0][3], w[0][5], w[0][7],
            C0, H0, h0o);

        // layer 1: x = [h0_new(512) | h1(256)], hid 256
        cfc_step_kernel<32, 32, 2><<<dim3(BQ / 32, H1 / 32), 256>>>(
            h0o, H0, H0,
            h1i, H1, H1,
            (const float*)nullptr, 0,
            pWc1, w[1][1], w[1][3], w[1][5], w[1][7],
            C1, H1, h1o);

        // layer 2: x = [h1_new(256) | h2(64)], hid 64
        cfc_step_kernel<32, 16, 1><<<dim3(BQ / 32, H2 / 16), 256>>>(
            h1o, H1, H1,
            h2i, H2, H2,
            (const float*)nullptr, 0,
            pWc2, w[2][1], w[2][3], w[2][5], w[2][7],
            C2, H2, h2o);
    }

    // final motor-layer state lives in ping buffer (KT & 1) == 0
    cudaMemcpyAsync(d_out, ph2, (size_t)BQ * H2 * sizeof(float), cudaMemcpyDeviceToDevice);
}

// round 3
// speedup vs baseline: 1.3700x; 1.3700x over previous
#include <cuda_runtime.h>
#include <math.h>
#include <stdint.h>

// Problem constants
#define BQ   512   // batch
#define KT   64    // timesteps
#define EBD  256
#define VFD  512
#define H0   512
#define H1   256
#define H2   64
#define C0   1280  // 768 + 512
#define C1   768   // 512 + 256
#define C2   320   // 256 + 64

// ---------------- device scratch (static, no allocation) ----------------
// Interleaved combined weights: Wc[k][4*j + m], m in {ff1,ff2,ta,tb}, mask folded into ff1/ff2.
__device__ float Wc0[(size_t)C0 * 4 * H0];
__device__ float Wc1[(size_t)C1 * 4 * H1];
__device__ float Wc2[(size_t)C2 * 4 * H2];
// Ping-pong hidden states
__device__ float h0b[2][BQ * H0];
__device__ float h1b[2][BQ * H1];
__device__ float h2b[2][BQ * H2];

// ---------------- weight prep: (hid,cat) row-major x4 -> (cat, 4*hid) interleaved ----------------
__global__ void prep_weights(const float* __restrict__ ff1, const float* __restrict__ ff2,
                             const float* __restrict__ ta,  const float* __restrict__ tb,
                             const float* __restrict__ mask,
                             float* __restrict__ dst, int hid, int cat)
{
    int idx = blockIdx.x * blockDim.x + threadIdx.x;
    if (idx >= hid * cat) return;
    int j = idx / cat;
    int k = idx - j * cat;
    float m = mask[idx];
    float* d = dst + (size_t)k * (4 * hid) + 4 * j;
    d[0] = ff1[idx] * m;
    d[1] = ff2[idx] * m;
    d[2] = ta[idx];
    d[3] = tb[idx];
}

// ---------------- tf32 helpers ----------------
__device__ __forceinline__ void mma_tf32(float* d, const uint32_t* a, const uint32_t* b)
{
    asm volatile(
        "mma.sync.aligned.m16n8k8.row.col.f32.tf32.tf32.f32 "
        "{%0,%1,%2,%3}, {%4,%5,%6,%7}, {%8,%9}, {%0,%1,%2,%3};\n"
        : "+f"(d[0]), "+f"(d[1]), "+f"(d[2]), "+f"(d[3])
        : "r"(a[0]), "r"(a[1]), "r"(a[2]), "r"(a[3]),
          "r"(b[0]), "r"(b[1]));
}

// hi = round-to-nearest tf32(v) as an fp32 bit pattern; lo = v - hi (exact)
__device__ __forceinline__ void tf32_split(float v, uint32_t& hi, uint32_t& lo)
{
    uint32_t h;
    asm("cvt.rna.tf32.f32 %0, %1;" : "=r"(h) : "f"(v));
    hi = h;
    float l = v - __uint_as_float(h);
    uint32_t lb;
    asm("cvt.rna.tf32.f32 %0, %1;" : "=r"(lb) : "f"(l));
    lo = lb;
}

// ---------------- fused GEMM (3xTF32 mma) + CfC epilogue ----------------
// C[M, 4*hid] = X[M, cat] @ Wc[cat, 4*hid]; epilogue combines groups of 4
// interleaved columns {ff1,ff2,ta,tb} into one CfC output per neuron.
// 3xTF32: acc += Ahi*Bhi + Ahi*Blo + Alo*Bhi  (fp32-grade accuracy).
template<int BM, int BN>
__global__ __launch_bounds__(128)
void cfc_mma_kernel(const float* __restrict__ seg0, int st0, int len0,
                    const float* __restrict__ seg1, int st1, int len1,
                    const float* __restrict__ seg2, int st2,
                    const float* __restrict__ Wc,
                    const float* __restrict__ bff1, const float* __restrict__ bff2,
                    const float* __restrict__ bta,  const float* __restrict__ btb,
                    int cat, int hid, float* __restrict__ hout)
{
    constexpr int BK  = 32;
    constexpr int TWM = BM / 2;          // warp tile rows   (2 warps along M)
    constexpr int TWN = BN / 2;          // warp tile cols   (2 warps along N)
    constexpr int MT  = TWM / 16;        // m16 subtiles per warp
    constexpr int NT  = TWN / 8;         // n8  subtiles per warp
    constexpr int AS  = BK + 4;          // As row stride
    constexpr int BS  = BN + 8;          // Bs row stride

    __shared__ float As[BM * AS];
    __shared__ float Bs[BK * BS];

    const int tid  = threadIdx.x;
    const int lane = tid & 31;
    const int wid  = tid >> 5;
    const int wm   = wid & 1;
    const int wn   = wid >> 1;
    const int g    = lane >> 2;   // 0..7
    const int tc   = lane & 3;    // 0..3

    const int rowBase = blockIdx.x * BM;
    const int colBase = blockIdx.y * BN;   // interleaved-column base
    const int l01 = len0 + len1;

    float acc[MT][NT][4];
    #pragma unroll
    for (int i = 0; i < MT; i++)
        #pragma unroll
        for (int q = 0; q < NT; q++)
            #pragma unroll
            for (int z = 0; z < 4; z++) acc[i][q][z] = 0.0f;

    const float4* WcV = reinterpret_cast<const float4*>(Wc);  // row k: hid float4s

    for (int k0 = 0; k0 < cat; k0 += BK) {
        // segment select (uniform per K-tile)
        const float* sp; int ss, so;
        if (k0 < len0)      { sp = seg0; ss = st0; so = k0; }
        else if (k0 < l01)  { sp = seg1; ss = st1; so = k0 - len0; }
        else                { sp = seg2; ss = st2; so = k0 - l01; }

        // stage A tile (BM x 32)
        constexpr int AV = BM * 8 / 128;
        #pragma unroll
        for (int i = 0; i < AV; i++) {
            int idx = tid + i * 128;
            int r = idx >> 3, c4 = idx & 7;
            float4 v = *reinterpret_cast<const float4*>(sp + (size_t)(rowBase + r) * ss + so + c4 * 4);
            *reinterpret_cast<float4*>(&As[r * AS + c4 * 4]) = v;
        }
        // stage B tile (32 x BN)
        constexpr int BNV = BN / 4;
        constexpr int BV  = 32 * BNV / 128;
        #pragma unroll
        for (int i = 0; i < BV; i++) {
            int idx = tid + i * 128;
            int r = idx / BNV, c4 = idx % BNV;
            float4 w = WcV[(size_t)(k0 + r) * hid + (colBase >> 2) + c4];
            *reinterpret_cast<float4*>(&Bs[r * BS + c4 * 4]) = w;
        }
        __syncthreads();

        #pragma unroll
        for (int k8 = 0; k8 < 4; k8++) {
            const int kb = k8 * 8;
            uint32_t ah[MT][4], al[MT][4];
            #pragma unroll
            for (int mt = 0; mt < MT; mt++) {
                const int wr = wm * TWM + mt * 16;
                tf32_split(As[(wr + g)     * AS + kb + tc],     ah[mt][0], al[mt][0]);
                tf32_split(As[(wr + g + 8) * AS + kb + tc],     ah[mt][1], al[mt][1]);
                tf32_split(As[(wr + g)     * AS + kb + tc + 4], ah[mt][2], al[mt][2]);
                tf32_split(As[(wr + g + 8) * AS + kb + tc + 4], ah[mt][3], al[mt][3]);
            }
            uint32_t bh[NT][2], bl[NT][2];
            #pragma unroll
            for (int nt = 0; nt < NT; nt++) {
                const int wc = wn * TWN + nt * 8 + g;
                tf32_split(Bs[(kb + tc)     * BS + wc], bh[nt][0], bl[nt][0]);
                tf32_split(Bs[(kb + tc + 4) * BS + wc], bh[nt][1], bl[nt][1]);
            }
            // pass 1: hi*hi
            #pragma unroll
            for (int mt = 0; mt < MT; mt++)
                #pragma unroll
                for (int nt = 0; nt < NT; nt++)
                    mma_tf32(acc[mt][nt], ah[mt], bh[nt]);
            // pass 2: hi*lo
            #pragma unroll
            for (int mt = 0; mt < MT; mt++)
                #pragma unroll
                for (int nt = 0; nt < NT; nt++)
                    mma_tf32(acc[mt][nt], ah[mt], bl[nt]);
            // pass 3: lo*hi
            #pragma unroll
            for (int mt = 0; mt < MT; mt++)
                #pragma unroll
                for (int nt = 0; nt < NT; nt++)
                    mma_tf32(acc[mt][nt], al[mt], bh[nt]);
        }
        __syncthreads();
    }

    // ---------------- CfC epilogue ----------------
    // D cols are interleaved {ff1,ff2,ta,tb}. Even lanes hold (ff1,ff2),
    // odd lanes hold (ta,tb) of the same neuron -> shfl_xor(1) pairs them.
    #pragma unroll
    for (int nt = 0; nt < NT; nt++) {
        const int cb = colBase + wn * TWN + nt * 8;
        const int j  = (cb >> 2) + (tc >> 1);   // neuron index (valid on even lanes)
        const float bf1 = bff1[j], bf2 = bff2[j], bt1 = bta[j], bt2 = btb[j];
        #pragma unroll
        for (int mt = 0; mt < MT; mt++) {
            const int r = rowBase + wm * TWM + mt * 16 + g;
            float d0 = acc[mt][nt][0], d1 = acc[mt][nt][1];
            float d2 = acc[mt][nt][2], d3 = acc[mt][nt][3];
            float o0 = __shfl_xor_sync(0xffffffffu, d0, 1);
            float o1 = __shfl_xor_sync(0xffffffffu, d1, 1);
            float o2 = __shfl_xor_sync(0xffffffffu, d2, 1);
            float o3 = __shfl_xor_sync(0xffffffffu, d3, 1);
            if (!(lane & 1)) {
                {
                    float f1 = tanhf(d0 + bf1);
                    float f2 = tanhf(d1 + bf2);
                    float s  = (o0 + bt1) + (o1 + bt2);
                    float ti = 1.0f / (1.0f + expf(-s));
                    hout[(size_t)r * hid + j] = f1 + ti * (f2 - f1);
                }
                {
                    float f1 = tanhf(d2 + bf1);
                    float f2 = tanhf(d3 + bf2);
                    float s  = (o2 + bt1) + (o3 + bt2);
                    float ti = 1.0f / (1.0f + expf(-s));
                    hout[(size_t)(r + 8) * hid + j] = f1 + ti * (f2 - f1);
                }
            }
        }
    }
}

// ---------------- host launcher ----------------
extern "C" void kernel_launch(void* const* d_in, const int* in_sizes, int n_in,
                              void* d_out, int out_size)
{
    const float* base = (const float*)d_in[0];
    const float* vis  = (const float*)d_in[1];
    // per layer: 0 ff1_w, 1 ff1_b, 2 ff2_w, 3 ff2_b, 4 ta_w, 5 ta_b, 6 tb_w, 7 tb_b, 8 mask
    const float* w[3][9];
    for (int li = 0; li < 3; li++)
        for (int q = 0; q < 9; q++)
            w[li][q] = (const float*)d_in[2 + li * 9 + q];

    float *pWc0, *pWc1, *pWc2, *ph0, *ph1, *ph2;
    cudaGetSymbolAddress((void**)&pWc0, Wc0);
    cudaGetSymbolAddress((void**)&pWc1, Wc1);
    cudaGetSymbolAddress((void**)&pWc2, Wc2);
    cudaGetSymbolAddress((void**)&ph0, h0b);
    cudaGetSymbolAddress((void**)&ph1, h1b);
    cudaGetSymbolAddress((void**)&ph2, h2b);

    // zero initial hidden states (ping buffer 0)
    cudaMemsetAsync(ph0, 0, (size_t)BQ * H0 * sizeof(float));
    cudaMemsetAsync(ph1, 0, (size_t)BQ * H1 * sizeof(float));
    cudaMemsetAsync(ph2, 0, (size_t)BQ * H2 * sizeof(float));

    // fold masks + interleave weights
    prep_weights<<<(H0 * C0 + 255) / 256, 256>>>(w[0][0], w[0][2], w[0][4], w[0][6], w[0][8], pWc0, H0, C0);
    prep_weights<<<(H1 * C1 + 255) / 256, 256>>>(w[1][0], w[1][2], w[1][4], w[1][6], w[1][8], pWc1, H1, C1);
    prep_weights<<<(H2 * C2 + 255) / 256, 256>>>(w[2][0], w[2][2], w[2][4], w[2][6], w[2][8], pWc2, H2, C2);

    for (int t = 0; t < KT; t++) {
        int pi = t & 1, po = (t + 1) & 1;
        float* h0i = ph0 + (size_t)pi * BQ * H0;
        float* h0o = ph0 + (size_t)po * BQ * H0;
        float* h1i = ph1 + (size_t)pi * BQ * H1;
        float* h1o = ph1 + (size_t)po * BQ * H1;
        float* h2i = ph2 + (size_t)pi * BQ * H2;
        float* h2o = ph2 + (size_t)po * BQ * H2;

        // layer 0: x = [base_t(256) | vis_t(512) | h0(512)], hid 512, N4=2048
        cfc_mma_kernel<64, 64><<<dim3(BQ / 64, (4 * H0) / 64), 128>>>(
            base + (size_t)t * EBD, KT * EBD, EBD,
            vis  + (size_t)t * VFD, KT * VFD, VFD,
            h0i, H0,
            pWc0, w[0][1], w[0][3], w[0][5], w[0][7],
            C0, H0, h0o);

        // layer 1: x = [h0_new(512) | h1(256)], hid 256, N4=1024
        cfc_mma_kernel<32, 64><<<dim3(BQ / 32, (4 * H1) / 64), 128>>>(
            h0o, H0, H0,
            h1i, H1, H1,
            (const float*)nullptr, 0,
            pWc1, w[1][1], w[1][3], w[1][5], w[1][7],
            C1, H1, h1o);

        // layer 2: x = [h1_new(256) | h2(64)], hid 64, N4=256
        cfc_mma_kernel<32, 32><<<dim3(BQ / 32, (4 * H2) / 32), 128>>>(
            h1o, H1, H1,
            h2i, H2, H2,
            (const float*)nullptr, 0,
            pWc2, w[2][1], w[2][3], w[2][5], w[2][7],
            C2, H2, h2o);
    }

    // final motor-layer state lives in ping buffer (KT & 1) == 0
    cudaMemcpyAsync(d_out, ph2, (size_t)BQ * H2 * sizeof(float), cudaMemcpyDeviceToDevice);
}

// round 4
// speedup vs baseline: 1.4809x; 1.0809x over previous
#include <cuda_runtime.h>
#include <math.h>
#include <stdint.h>

// Problem constants
#define BQ   512   // batch
#define KT   64    // timesteps
#define EBD  256
#define VFD  512
#define SENS 768
#define H0   512
#define H1   256
#define H2   64
#define C0   1280  // 768 + 512
#define C1   768   // 512 + 256
#define C2   320   // 256 + 64

// ---------------- device scratch (static, no allocation) ----------------
// Everything kept as float2 {tf32_hi, tf32_lo} for 3xTF32 MMA.
__device__ float2 X2g[(size_t)BQ * KT * SENS];          // split sensory inputs (201MB)
__device__ float2 Wc2_0[(size_t)C0 * 4 * H0];           // split interleaved weights
__device__ float2 Wc2_1[(size_t)C1 * 4 * H1];
__device__ float2 Wc2_2[(size_t)C2 * 4 * H2];
__device__ float2 h0b2[2][BQ * H0];                     // ping-pong split hidden states
__device__ float2 h1b2[2][BQ * H1];
__device__ float2 h2b2[2][BQ * H2];

// ---------------- split helpers ----------------
__device__ __forceinline__ float2 tf32_split2(float v)
{
    uint32_t h, l;
    asm("cvt.rna.tf32.f32 %0, %1;" : "=r"(h) : "f"(v));
    float hv = __uint_as_float(h);
    asm("cvt.rna.tf32.f32 %0, %1;" : "=r"(l) : "f"(v - hv));
    return make_float2(hv, __uint_as_float(l));
}

__device__ __forceinline__ void mma_tf32(float* d, const uint32_t* a, const uint32_t* b)
{
    asm volatile(
        "mma.sync.aligned.m16n8k8.row.col.f32.tf32.tf32.f32 "
        "{%0,%1,%2,%3}, {%4,%5,%6,%7}, {%8,%9}, {%0,%1,%2,%3};\n"
        : "+f"(d[0]), "+f"(d[1]), "+f"(d[2]), "+f"(d[3])
        : "r"(a[0]), "r"(a[1]), "r"(a[2]), "r"(a[3]),
          "r"(b[0]), "r"(b[1]));
}

__device__ __forceinline__ void cpa16(void* dst_smem, const void* src_gmem)
{
    uint32_t d = (uint32_t)__cvta_generic_to_shared(dst_smem);
    asm volatile("cp.async.cg.shared.global [%0], [%1], 16;\n" :: "r"(d), "l"(src_gmem));
}
__device__ __forceinline__ void cpa_commit() { asm volatile("cp.async.commit_group;\n"); }

// ---------------- prep kernels ----------------
__global__ void prep_weights2(const float* __restrict__ ff1, const float* __restrict__ ff2,
                              const float* __restrict__ ta,  const float* __restrict__ tb,
                              const float* __restrict__ mask,
                              float2* __restrict__ dst, int hid, int cat)
{
    int idx = blockIdx.x * blockDim.x + threadIdx.x;
    if (idx >= hid * cat) return;
    int j = idx / cat;
    int k = idx - j * cat;
    float m = mask[idx];
    float2* d = dst + (size_t)k * (4 * hid) + 4 * j;
    d[0] = tf32_split2(ff1[idx] * m);
    d[1] = tf32_split2(ff2[idx] * m);
    d[2] = tf32_split2(ta[idx]);
    d[3] = tf32_split2(tb[idx]);
}

__global__ void prep_inputs(const float* __restrict__ base, const float* __restrict__ vis,
                            float2* __restrict__ dst)
{
    size_t idx = (size_t)blockIdx.x * blockDim.x + threadIdx.x;
    if (idx >= (size_t)BQ * KT * SENS) return;
    size_t row = idx / SENS;
    int c = (int)(idx - row * SENS);
    float v = (c < EBD) ? base[row * EBD + c] : vis[row * VFD + (c - EBD)];
    dst[idx] = tf32_split2(v);
}

__global__ void extract_out(const float2* __restrict__ h, float* __restrict__ out, int n)
{
    int i = blockIdx.x * blockDim.x + threadIdx.x;
    if (i < n) out[i] = h[i].x + h[i].y;
}

// ---------------- fused GEMM (3xTF32) + CfC epilogue ----------------
// C[M, 4*hid] = X[M, cat] @ Wc[cat, 4*hid], X rows concatenated from <=2
// float2 segments. All operands pre-split {hi,lo}; inner loop is LDS.64+HMMA
// only. cp.async double-buffered K pipeline.
template<int BM, int BN>
__global__ __launch_bounds__(128)
void cfc_mma2(const float2* __restrict__ seg0, int st0, int len0,
              const float2* __restrict__ seg1, int st1,
              const float2* __restrict__ Wc2,
              const float* __restrict__ bff1, const float* __restrict__ bff2,
              const float* __restrict__ bta,  const float* __restrict__ btb,
              int cat, int hid, float2* __restrict__ hout)
{
    constexpr int BK  = 32;
    constexpr int TWM = BM / 2;          // 2 warps along M
    constexpr int TWN = BN / 2;          // 2 warps along N
    constexpr int MT  = TWM / 16;
    constexpr int NT  = TWN / 8;
    constexpr int AS  = 36;              // float2 stride (=4 mod 16 -> conflict-free)
    constexpr int BS  = BN + 4;          // float2 stride (=4 mod 16)
    constexpr int ASZ = BM * AS;
    constexpr int BSZ = BK * BS;

    extern __shared__ float2 smem[];     // [2*ASZ | 2*BSZ]

    const int tid  = threadIdx.x;
    const int lane = tid & 31;
    const int wid  = tid >> 5;
    const int wm   = wid & 1;
    const int wn   = wid >> 1;
    const int g    = lane >> 2;   // 0..7
    const int tc   = lane & 3;    // 0..3

    const int rowBase = blockIdx.x * BM;
    const int colBase = blockIdx.y * BN;   // interleaved-column base
    const int ncol = 4 * hid;

    float acc[MT][NT][4];
    #pragma unroll
    for (int i = 0; i < MT; i++)
        #pragma unroll
        for (int q = 0; q < NT; q++)
            #pragma unroll
            for (int z = 0; z < 4; z++) acc[i][q][z] = 0.0f;

    // ---- tile loader (cp.async, 16B chunks = 2 float2) ----
    auto load_tiles = [&](int k0, int buf) {
        const float2* sp; int ss, so;
        if (k0 < len0) { sp = seg0; ss = st0; so = k0; }
        else           { sp = seg1; ss = st1; so = k0 - len0; }
        float2* As = smem + buf * ASZ;
        float2* Bs = smem + 2 * ASZ + buf * BSZ;
        // A: BM rows x 32 float2 -> BM*16 chunks
        #pragma unroll
        for (int i = 0; i < BM * 16 / 128; i++) {
            int idx = tid + i * 128;
            int r = idx >> 4, c2 = (idx & 15) * 2;
            cpa16(As + r * AS + c2, sp + (size_t)(rowBase + r) * ss + so + c2);
        }
        // B: 32 rows x BN float2 -> 32*(BN/2) chunks
        #pragma unroll
        for (int i = 0; i < 32 * (BN / 2) / 128; i++) {
            int idx = tid + i * 128;
            int r = idx / (BN / 2), c2 = (idx % (BN / 2)) * 2;
            cpa16(Bs + r * BS + c2, Wc2 + (size_t)(k0 + r) * ncol + colBase + c2);
        }
        cpa_commit();
    };

    load_tiles(0, 0);

    const int ntile = cat / BK;
    int buf = 0;
    for (int it = 0; it < ntile; it++, buf ^= 1) {
        if (it + 1 < ntile) {
            load_tiles((it + 1) * BK, buf ^ 1);
            asm volatile("cp.async.wait_group 1;\n");
        } else {
            asm volatile("cp.async.wait_group 0;\n");
        }
        __syncthreads();

        const float2* As = smem + buf * ASZ;
        const float2* Bs = smem + 2 * ASZ + buf * BSZ;

        #pragma unroll
        for (int k8 = 0; k8 < 4; k8++) {
            const int kb = k8 * 8;
            uint32_t ah[MT][4], al[MT][4];
            #pragma unroll
            for (int mt = 0; mt < MT; mt++) {
                const int wr = wm * TWM + mt * 16;
                float2 p0 = As[(wr + g)     * AS + kb + tc];
                float2 p1 = As[(wr + g + 8) * AS + kb + tc];
                float2 p2 = As[(wr + g)     * AS + kb + tc + 4];
                float2 p3 = As[(wr + g + 8) * AS + kb + tc + 4];
                ah[mt][0] = __float_as_uint(p0.x); al[mt][0] = __float_as_uint(p0.y);
                ah[mt][1] = __float_as_uint(p1.x); al[mt][1] = __float_as_uint(p1.y);
                ah[mt][2] = __float_as_uint(p2.x); al[mt][2] = __float_as_uint(p2.y);
                ah[mt][3] = __float_as_uint(p3.x); al[mt][3] = __float_as_uint(p3.y);
            }
            uint32_t bh[NT][2], bl[NT][2];
            #pragma unroll
            for (int nt = 0; nt < NT; nt++) {
                const int wc = wn * TWN + nt * 8 + g;
                float2 q0 = Bs[(kb + tc)     * BS + wc];
                float2 q1 = Bs[(kb + tc + 4) * BS + wc];
                bh[nt][0] = __float_as_uint(q0.x); bl[nt][0] = __float_as_uint(q0.y);
                bh[nt][1] = __float_as_uint(q1.x); bl[nt][1] = __float_as_uint(q1.y);
            }
            #pragma unroll
            for (int mt = 0; mt < MT; mt++)
                #pragma unroll
                for (int nt = 0; nt < NT; nt++)
                    mma_tf32(acc[mt][nt], ah[mt], bh[nt]);
            #pragma unroll
            for (int mt = 0; mt < MT; mt++)
                #pragma unroll
                for (int nt = 0; nt < NT; nt++)
                    mma_tf32(acc[mt][nt], ah[mt], bl[nt]);
            #pragma unroll
            for (int mt = 0; mt < MT; mt++)
                #pragma unroll
                for (int nt = 0; nt < NT; nt++)
                    mma_tf32(acc[mt][nt], al[mt], bh[nt]);
        }
        __syncthreads();
    }

    // ---------------- CfC epilogue ----------------
    // Even lanes hold (ff1,ff2), odd lanes (ta,tb) of the same neuron.
    #pragma unroll
    for (int nt = 0; nt < NT; nt++) {
        const int cb = colBase + wn * TWN + nt * 8;
        const int j  = (cb >> 2) + (tc >> 1);
        const float bf1 = bff1[j], bf2 = bff2[j], bt1 = bta[j], bt2 = btb[j];
        #pragma unroll
        for (int mt = 0; mt < MT; mt++) {
            const int r = rowBase + wm * TWM + mt * 16 + g;
            float d0 = acc[mt][nt][0], d1 = acc[mt][nt][1];
            float d2 = acc[mt][nt][2], d3 = acc[mt][nt][3];
            float o0 = __shfl_xor_sync(0xffffffffu, d0, 1);
            float o1 = __shfl_xor_sync(0xffffffffu, d1, 1);
            float o2 = __shfl_xor_sync(0xffffffffu, d2, 1);
            float o3 = __shfl_xor_sync(0xffffffffu, d3, 1);
            if (!(lane & 1)) {
                {
                    float f1 = tanhf(d0 + bf1);
                    float f2 = tanhf(d1 + bf2);
                    float s  = (o0 + bt1) + (o1 + bt2);
                    float ti = 1.0f / (1.0f + expf(-s));
                    hout[(size_t)r * hid + j] = tf32_split2(f1 + ti * (f2 - f1));
                }
                {
                    float f1 = tanhf(d2 + bf1);
                    float f2 = tanhf(d3 + bf2);
                    float s  = (o2 + bt1) + (o3 + bt2);
                    float ti = 1.0f / (1.0f + expf(-s));
                    hout[(size_t)(r + 8) * hid + j] = tf32_split2(f1 + ti * (f2 - f1));
                }
            }
        }
    }
}

// ---------------- host launcher ----------------
extern "C" void kernel_launch(void* const* d_in, const int* in_sizes, int n_in,
                              void* d_out, int out_size)
{
    const float* base = (const float*)d_in[0];
    const float* vis  = (const float*)d_in[1];
    // per layer: 0 ff1_w, 1 ff1_b, 2 ff2_w, 3 ff2_b, 4 ta_w, 5 ta_b, 6 tb_w, 7 tb_b, 8 mask
    const float* w[3][9];
    for (int li = 0; li < 3; li++)
        for (int q = 0; q < 9; q++)
            w[li][q] = (const float*)d_in[2 + li * 9 + q];

    float2 *pX2, *pW0, *pW1, *pW2, *ph0, *ph1, *ph2;
    cudaGetSymbolAddress((void**)&pX2, X2g);
    cudaGetSymbolAddress((void**)&pW0, Wc2_0);
    cudaGetSymbolAddress((void**)&pW1, Wc2_1);
    cudaGetSymbolAddress((void**)&pW2, Wc2_2);
    cudaGetSymbolAddress((void**)&ph0, h0b2);
    cudaGetSymbolAddress((void**)&ph1, h1b2);
    cudaGetSymbolAddress((void**)&ph2, h2b2);

    // raise dynamic smem limits (idempotent host-side calls)
    constexpr int SM0 = (2 * 64 * 36 + 2 * 32 * 68) * (int)sizeof(float2);  // 71680
    constexpr int SM1 = (2 * 32 * 36 + 2 * 32 * 68) * (int)sizeof(float2);  // 53248
    constexpr int SM2 = (2 * 32 * 36 + 2 * 32 * 36) * (int)sizeof(float2);  // 36864
    cudaFuncSetAttribute((const void*)cfc_mma2<64, 64>, cudaFuncAttributeMaxDynamicSharedMemorySize, SM0);
    cudaFuncSetAttribute((const void*)cfc_mma2<32, 64>, cudaFuncAttributeMaxDynamicSharedMemorySize, SM1);
    cudaFuncSetAttribute((const void*)cfc_mma2<32, 32>, cudaFuncAttributeMaxDynamicSharedMemorySize, SM2);

    // zero initial hidden states (ping buffer 0)
    cudaMemsetAsync(ph0, 0, (size_t)BQ * H0 * sizeof(float2));
    cudaMemsetAsync(ph1, 0, (size_t)BQ * H1 * sizeof(float2));
    cudaMemsetAsync(ph2, 0, (size_t)BQ * H2 * sizeof(float2));

    // prep: split inputs + fold masks / split + interleave weights
    {
        size_t n = (size_t)BQ * KT * SENS;
        prep_inputs<<<(unsigned)((n + 255) / 256), 256>>>(base, vis, pX2);
    }
    prep_weights2<<<(H0 * C0 + 255) / 256, 256>>>(w[0][0], w[0][2], w[0][4], w[0][6], w[0][8], pW0, H0, C0);
    prep_weights2<<<(H1 * C1 + 255) / 256, 256>>>(w[1][0], w[1][2], w[1][4], w[1][6], w[1][8], pW1, H1, C1);
    prep_weights2<<<(H2 * C2 + 255) / 256, 256>>>(w[2][0], w[2][2], w[2][4], w[2][6], w[2][8], pW2, H2, C2);

    for (int t = 0; t < KT; t++) {
        int pi = t & 1, po = (t + 1) & 1;
        float2* h0i = ph0 + (size_t)pi * BQ * H0;
        float2* h0o = ph0 + (size_t)po * BQ * H0;
        float2* h1i = ph1 + (size_t)pi * BQ * H1;
        float2* h1o = ph1 + (size_t)po * BQ * H1;
        float2* h2i = ph2 + (size_t)pi * BQ * H2;
        float2* h2o = ph2 + (size_t)po * BQ * H2;

        // layer 0: x = [sens_t(768) | h0(512)]
        cfc_mma2<64, 64><<<dim3(BQ / 64, (4 * H0) / 64), 128, SM0>>>(
            pX2 + (size_t)t * SENS, KT * SENS, SENS,
            h0i, H0,
            pW0, w[0][1], w[0][3], w[0][5], w[0][7],
            C0, H0, h0o);

        // layer 1: x = [h0_new(512) | h1(256)]
        cfc_mma2<32, 64><<<dim3(BQ / 32, (4 * H1) / 64), 128, SM1>>>(
            h0o, H0, H0,
            h1i, H1,
            pW1, w[1][1], w[1][3], w[1][5], w[1][7],
            C1, H1, h1o);

        // layer 2: x = [h1_new(256) | h2(64)]
        cfc_mma2<32, 32><<<dim3(BQ / 32, (4 * H2) / 32), 128, SM2>>>(
            h1o, H1, H1,
            h2i, H2,
            pW2, w[2][1], w[2][3], w[2][5], w[2][7],
            C2, H2, h2o);
    }

    // final motor-layer state (ping buffer 0): hi+lo -> fp32 output
    extract_out<<<(BQ * H2 + 255) / 256, 256>>>(ph2, (float*)d_out, BQ * H2);
}

// round 7
// speedup vs baseline: 2.2073x; 1.4905x over previous
#include <cuda_runtime.h>
#include <cuda_bf16.h>
#include <math.h>
#include <stdint.h>

// Problem constants
#define BQ   512   // batch
#define KT   64    // timesteps
#define EBD  256
#define VFD  512
#define SENS 768
#define H0   512
#define H1   256
#define H2   64
#define C0   1280  // 768 + 512
#define C1   768   // 512 + 256
#define C2   320   // 256 + 64

// ---------------- device scratch (static, no allocation) ----------------
// hi/lo bf16 planes for 3xBF16 emulated-fp32 MMA.
__device__ __align__(16) __nv_bfloat16 Xh[(size_t)BQ * KT * SENS];
__device__ __align__(16) __nv_bfloat16 Xl[(size_t)BQ * KT * SENS];
// Weights: [4*hid][cat] rows interleaved {ff1,ff2,ta,tb}, k contiguous.
__device__ __align__(16) __nv_bfloat16 W0h[(size_t)4 * H0 * C0];
__device__ __align__(16) __nv_bfloat16 W0l[(size_t)4 * H0 * C0];
__device__ __align__(16) __nv_bfloat16 W1h[(size_t)4 * H1 * C1];
__device__ __align__(16) __nv_bfloat16 W1l[(size_t)4 * H1 * C1];
__device__ __align__(16) __nv_bfloat16 W2h[(size_t)4 * H2 * C2];
__device__ __align__(16) __nv_bfloat16 W2l[(size_t)4 * H2 * C2];
// Ping-pong hidden states, hi/lo planes
__device__ __align__(16) __nv_bfloat16 h0h[2][BQ * H0];
__device__ __align__(16) __nv_bfloat16 h0l[2][BQ * H0];
__device__ __align__(16) __nv_bfloat16 h1h[2][BQ * H1];
__device__ __align__(16) __nv_bfloat16 h1l[2][BQ * H1];
__device__ __align__(16) __nv_bfloat16 h2h[2][BQ * H2];
__device__ __align__(16) __nv_bfloat16 h2l[2][BQ * H2];

// ---------------- helpers ----------------
__device__ __forceinline__ void bf16_split(float v, __nv_bfloat16& hi, __nv_bfloat16& lo)
{
    hi = __float2bfloat16(v);
    lo = __float2bfloat16(v - __bfloat162float(hi));
}

__device__ __forceinline__ void mma_bf16(float* d, const uint32_t* a, const uint32_t* b)
{
    asm volatile(
        "mma.sync.aligned.m16n8k16.row.col.f32.bf16.bf16.f32 "
        "{%0,%1,%2,%3}, {%4,%5,%6,%7}, {%8,%9}, {%0,%1,%2,%3};\n"
        : "+f"(d[0]), "+f"(d[1]), "+f"(d[2]), "+f"(d[3])
        : "r"(a[0]), "r"(a[1]), "r"(a[2]), "r"(a[3]),
          "r"(b[0]), "r"(b[1]));
}

__device__ __forceinline__ void cpa16(uint32_t* dst_smem, const void* src_gmem)
{
    uint32_t d = (uint32_t)__cvta_generic_to_shared(dst_smem);
    asm volatile("cp.async.cg.shared.global [%0], [%1], 16;\n" :: "r"(d), "l"(src_gmem));
}

// ---------------- prep kernels ----------------
__global__ void prep_weights_bf(const float* __restrict__ ff1, const float* __restrict__ ff2,
                                const float* __restrict__ ta,  const float* __restrict__ tb,
                                const float* __restrict__ mask,
                                __nv_bfloat16* __restrict__ dh, __nv_bfloat16* __restrict__ dl,
                                int hid, int cat)
{
    int idx = blockIdx.x * blockDim.x + threadIdx.x;
    if (idx >= hid * cat) return;
    int j = idx / cat;
    int k = idx - j * cat;
    float m = mask[idx];
    float v[4] = { ff1[idx] * m, ff2[idx] * m, ta[idx], tb[idx] };
    #pragma unroll
    for (int q = 0; q < 4; q++) {
        __nv_bfloat16 hi, lo;
        bf16_split(v[q], hi, lo);
        size_t o = (size_t)(4 * j + q) * cat + k;
        dh[o] = hi; dl[o] = lo;
    }
}

__global__ void prep_inputs_bf(const float* __restrict__ base, const float* __restrict__ vis,
                               __nv_bfloat16* __restrict__ xh, __nv_bfloat16* __restrict__ xl)
{
    size_t idx = (size_t)blockIdx.x * blockDim.x + threadIdx.x;
    if (idx >= (size_t)BQ * KT * SENS) return;
    size_t row = idx / SENS;
    int c = (int)(idx - row * SENS);
    float v = (c < EBD) ? base[row * EBD + c] : vis[row * VFD + (c - EBD)];
    __nv_bfloat16 hi, lo;
    bf16_split(v, hi, lo);
    xh[idx] = hi; xl[idx] = lo;
}

__global__ void extract_out(const __nv_bfloat16* __restrict__ hh,
                            const __nv_bfloat16* __restrict__ hl,
                            float* __restrict__ out, int n)
{
    int i = blockIdx.x * blockDim.x + threadIdx.x;
    if (i < n) out[i] = __bfloat162float(hh[i]) + __bfloat162float(hl[i]);
}

// ---------------- fused GEMM (3xBF16, m16n8k16) + CfC epilogue ----------------
// C[M, 4*hid] = X[M, cat] @ W[cat, 4*hid]; W stored [4*hid][cat] (k contig).
// acc += Ahi*Bhi + Ahi*Blo + Alo*Bhi. Epilogue combines 4 interleaved cols
// {ff1,ff2,ta,tb} into one CfC output; even lanes(ff) pair odd lanes(t) via shfl.
template<int BM, int BN>
__global__ __launch_bounds__(128)
void cfc_mma_bf(const __nv_bfloat16* __restrict__ s0h, const __nv_bfloat16* __restrict__ s0l,
                int st0, int len0,
                const __nv_bfloat16* __restrict__ s1h, const __nv_bfloat16* __restrict__ s1l,
                int st1,
                const __nv_bfloat16* __restrict__ Wh, const __nv_bfloat16* __restrict__ Wl,
                const float* __restrict__ bff1, const float* __restrict__ bff2,
                const float* __restrict__ bta,  const float* __restrict__ btb,
                int cat, int hid,
                __nv_bfloat16* __restrict__ oh, __nv_bfloat16* __restrict__ ol)
{
    constexpr int BK  = 32;              // K per tile (bf16 elements)
    constexpr int TWM = BM / 2;          // 2 warps along M
    constexpr int TWN = BN / 2;          // 2 warps along N
    constexpr int MT  = TWM / 16;
    constexpr int NT  = TWN / 8;
    constexpr int RS  = 20;              // row stride in uint32 (40 bf16): conflict-free
    constexpr int APL = BM * RS;         // A plane size (uint32)
    constexpr int BPL = BN * RS;         // B plane size (uint32)

    extern __shared__ __align__(16) uint32_t sm32[];
    // layout: Ahi[2] | Alo[2] | Bhi[2] | Blo[2]

    const int tid  = threadIdx.x;
    const int lane = tid & 31;
    const int wid  = tid >> 5;
    const int wm   = wid & 1;
    const int wn   = wid >> 1;
    const int g    = lane >> 2;   // 0..7
    const int tc   = lane & 3;    // 0..3

    const int rowBase = blockIdx.x * BM;
    const int colBase = blockIdx.y * BN;   // interleaved-column base
    const int l0 = len0;

    float acc[MT][NT][4];
    #pragma unroll
    for (int i = 0; i < MT; i++)
        #pragma unroll
        for (int q = 0; q < NT; q++)
            #pragma unroll
            for (int z = 0; z < 4; z++) acc[i][q][z] = 0.0f;

    auto load_tiles = [&](int k0, int buf) {
        const __nv_bfloat16 *shi, *slo; int ss, so;
        if (k0 < l0) { shi = s0h; slo = s0l; ss = st0; so = k0; }
        else         { shi = s1h; slo = s1l; ss = st1; so = k0 - l0; }
        uint32_t* Ah = sm32 + buf * APL;
        uint32_t* Al = sm32 + 2 * APL + buf * APL;
        #pragma unroll
        for (int i = 0; i < BM * 4 / 128; i++) {
            int idx = tid + i * 128;
            int r = idx >> 2, c = idx & 3;
            size_t go = (size_t)(rowBase + r) * ss + so + c * 8;
            cpa16(Ah + r * RS + c * 4, shi + go);
            cpa16(Al + r * RS + c * 4, slo + go);
        }
        uint32_t* Bh = sm32 + 4 * APL + buf * BPL;
        uint32_t* Bl = sm32 + 4 * APL + 2 * BPL + buf * BPL;
        #pragma unroll
        for (int i = 0; i < BN * 4 / 128; i++) {
            int idx = tid + i * 128;
            int r = idx >> 2, c = idx & 3;
            size_t go = (size_t)(colBase + r) * cat + k0 + c * 8;
            cpa16(Bh + r * RS + c * 4, Wh + go);
            cpa16(Bl + r * RS + c * 4, Wl + go);
        }
        asm volatile("cp.async.commit_group;\n");
    };

    load_tiles(0, 0);

    const int ntile = cat / BK;
    int buf = 0;
    for (int it = 0; it < ntile; it++, buf ^= 1) {
        if (it + 1 < ntile) {
            load_tiles((it + 1) * BK, buf ^ 1);
            asm volatile("cp.async.wait_group 1;\n");
        } else {
            asm volatile("cp.async.wait_group 0;\n");
        }
        __syncthreads();

        const uint32_t* Ah = sm32 + buf * APL;
        const uint32_t* Al = sm32 + 2 * APL + buf * APL;
        const uint32_t* Bh = sm32 + 4 * APL + buf * BPL;
        const uint32_t* Bl = sm32 + 4 * APL + 2 * BPL + buf * BPL;

        #pragma unroll
        for (int k16 = 0; k16 < 2; k16++) {
            const int kb = k16 * 8;   // uint32 offset within row
            uint32_t ah[MT][4], al[MT][4];
            #pragma unroll
            for (int mt = 0; mt < MT; mt++) {
                const int r0 = (wm * TWM + mt * 16 + g) * RS + kb + tc;
                ah[mt][0] = Ah[r0];
                ah[mt][1] = Ah[r0 + 8 * RS];
                ah[mt][2] = Ah[r0 + 4];
                ah[mt][3] = Ah[r0 + 8 * RS + 4];
                al[mt][0] = Al[r0];
                al[mt][1] = Al[r0 + 8 * RS];
                al[mt][2] = Al[r0 + 4];
                al[mt][3] = Al[r0 + 8 * RS + 4];
            }
            uint32_t bh[NT][2], bl[NT][2];
            #pragma unroll
            for (int nt = 0; nt < NT; nt++) {
                const int c0 = (wn * TWN + nt * 8 + g) * RS + kb + tc;
                bh[nt][0] = Bh[c0];
                bh[nt][1] = Bh[c0 + 4];
                bl[nt][0] = Bl[c0];
                bl[nt][1] = Bl[c0 + 4];
            }
            #pragma unroll
            for (int mt = 0; mt < MT; mt++)
                #pragma unroll
                for (int nt = 0; nt < NT; nt++)
                    mma_bf16(acc[mt][nt], ah[mt], bh[nt]);
            #pragma unroll
            for (int mt = 0; mt < MT; mt++)
                #pragma unroll
                for (int nt = 0; nt < NT; nt++)
                    mma_bf16(acc[mt][nt], ah[mt], bl[nt]);
            #pragma unroll
            for (int mt = 0; mt < MT; mt++)
                #pragma unroll
                for (int nt = 0; nt < NT; nt++)
                    mma_bf16(acc[mt][nt], al[mt], bh[nt]);
        }
        __syncthreads();
    }

    // ---------------- CfC epilogue ----------------
    #pragma unroll
    for (int nt = 0; nt < NT; nt++) {
        const int cb = colBase + wn * TWN + nt * 8;
        const int j  = (cb >> 2) + (tc >> 1);   // neuron (valid on even lanes)
        const float bf1 = bff1[j], bf2 = bff2[j], bt1 = bta[j], bt2 = btb[j];
        #pragma unroll
        for (int mt = 0; mt < MT; mt++) {
            const int r = rowBase + wm * TWM + mt * 16 + g;
            float d0 = acc[mt][nt][0], d1 = acc[mt][nt][1];
            float d2 = acc[mt][nt][2], d3 = acc[mt][nt][3];
            float o0 = __shfl_xor_sync(0xffffffffu, d0, 1);
            float o1 = __shfl_xor_sync(0xffffffffu, d1, 1);
            float o2 = __shfl_xor_sync(0xffffffffu, d2, 1);
            float o3 = __shfl_xor_sync(0xffffffffu, d3, 1);
            if (!(lane & 1)) {
                {
                    float f1 = tanhf(d0 + bf1);
                    float f2 = tanhf(d1 + bf2);
                    float s  = (o0 + bt1) + (o1 + bt2);
                    float ti = 1.0f / (1.0f + expf(-s));
                    float v  = f1 + ti * (f2 - f1);
                    __nv_bfloat16 hi, lo; bf16_split(v, hi, lo);
                    oh[(size_t)r * hid + j] = hi;
                    ol[(size_t)r * hid + j] = lo;
                }
                {
                    float f1 = tanhf(d2 + bf1);
                    float f2 = tanhf(d3 + bf2);
                    float s  = (o2 + bt1) + (o3 + bt2);
                    float ti = 1.0f / (1.0f + expf(-s));
                    float v  = f1 + ti * (f2 - f1);
                    __nv_bfloat16 hi, lo; bf16_split(v, hi, lo);
                    oh[(size_t)(r + 8) * hid + j] = hi;
                    ol[(size_t)(r + 8) * hid + j] = lo;
                }
            }
        }
    }
}

// ---------------- host launcher ----------------
extern "C" void kernel_launch(void* const* d_in, const int* in_sizes, int n_in,
                              void* d_out, int out_size)
{
    const float* base = (const float*)d_in[0];
    const float* vis  = (const float*)d_in[1];
    // per layer: 0 ff1_w, 1 ff1_b, 2 ff2_w, 3 ff2_b, 4 ta_w, 5 ta_b, 6 tb_w, 7 tb_b, 8 mask
    const float* w[3][9];
    for (int li = 0; li < 3; li++)
        for (int q = 0; q < 9; q++)
            w[li][q] = (const float*)d_in[2 + li * 9 + q];

    __nv_bfloat16 *pXh, *pXl, *pW0h, *pW0l, *pW1h, *pW1l, *pW2h, *pW2l;
    __nv_bfloat16 *p0h, *p0l, *p1h, *p1l, *p2h, *p2l;
    cudaGetSymbolAddress((void**)&pXh, Xh);   cudaGetSymbolAddress((void**)&pXl, Xl);
    cudaGetSymbolAddress((void**)&pW0h, W0h); cudaGetSymbolAddress((void**)&pW0l, W0l);
    cudaGetSymbolAddress((void**)&pW1h, W1h); cudaGetSymbolAddress((void**)&pW1l, W1l);
    cudaGetSymbolAddress((void**)&pW2h, W2h); cudaGetSymbolAddress((void**)&pW2l, W2l);
    cudaGetSymbolAddress((void**)&p0h, h0h);  cudaGetSymbolAddress((void**)&p0l, h0l);
    cudaGetSymbolAddress((void**)&p1h, h1h);  cudaGetSymbolAddress((void**)&p1l, h1l);
    cudaGetSymbolAddress((void**)&p2h, h2h);  cudaGetSymbolAddress((void**)&p2l, h2l);

    // smem sizes: (BM+BN)*4 planes*40 bf16*2B = (BM+BN)*320 bytes
    constexpr int SM0 = (64 + 64) * 320;   // 40960
    constexpr int SM1 = (32 + 64) * 320;   // 30720
    constexpr int SM2 = (32 + 32) * 320;   // 20480

    // zero initial hidden states (ping buffer 0)
    cudaMemsetAsync(p0h, 0, (size_t)BQ * H0 * sizeof(__nv_bfloat16));
    cudaMemsetAsync(p0l, 0, (size_t)BQ * H0 * sizeof(__nv_bfloat16));
    cudaMemsetAsync(p1h, 0, (size_t)BQ * H1 * sizeof(__nv_bfloat16));
    cudaMemsetAsync(p1l, 0, (size_t)BQ * H1 * sizeof(__nv_bfloat16));
    cudaMemsetAsync(p2h, 0, (size_t)BQ * H2 * sizeof(__nv_bfloat16));
    cudaMemsetAsync(p2l, 0, (size_t)BQ * H2 * sizeof(__nv_bfloat16));

    // prep
    {
        size_t n = (size_t)BQ * KT * SENS;
        prep_inputs_bf<<<(unsigned)((n + 255) / 256), 256>>>(base, vis, pXh, pXl);
    }
    prep_weights_bf<<<(H0 * C0 + 255) / 256, 256>>>(w[0][0], w[0][2], w[0][4], w[0][6], w[0][8], pW0h, pW0l, H0, C0);
    prep_weights_bf<<<(H1 * C1 + 255) / 256, 256>>>(w[1][0], w[1][2], w[1][4], w[1][6], w[1][8], pW1h, pW1l, H1, C1);
    prep_weights_bf<<<(H2 * C2 + 255) / 256, 256>>>(w[2][0], w[2][2], w[2][4], w[2][6], w[2][8], pW2h, pW2l, H2, C2);

    for (int t = 0; t < KT; t++) {
        int pi = t & 1, po = (t + 1) & 1;
        __nv_bfloat16* h0ih = p0h + (size_t)pi * BQ * H0;  __nv_bfloat16* h0il = p0l + (size_t)pi * BQ * H0;
        __nv_bfloat16* h0oh = p0h + (size_t)po * BQ * H0;  __nv_bfloat16* h0ol = p0l + (size_t)po * BQ * H0;
        __nv_bfloat16* h1ih = p1h + (size_t)pi * BQ * H1;  __nv_bfloat16* h1il = p1l + (size_t)pi * BQ * H1;
        __nv_bfloat16* h1oh = p1h + (size_t)po * BQ * H1;  __nv_bfloat16* h1ol = p1l + (size_t)po * BQ * H1;
        __nv_bfloat16* h2ih = p2h + (size_t)pi * BQ * H2;  __nv_bfloat16* h2il = p2l + (size_t)pi * BQ * H2;
        __nv_bfloat16* h2oh = p2h + (size_t)po * BQ * H2;  __nv_bfloat16* h2ol = p2l + (size_t)po * BQ * H2;

        // layer 0: x = [sens_t(768) | h0(512)]
        cfc_mma_bf<64, 64><<<dim3(BQ / 64, (4 * H0) / 64), 128, SM0>>>(
            pXh + (size_t)t * SENS, pXl + (size_t)t * SENS, KT * SENS, SENS,
            h0ih, h0il, H0,
            pW0h, pW0l, w[0][1], w[0][3], w[0][5], w[0][7],
            C0, H0, h0oh, h0ol);

        // layer 1: x = [h0_new(512) | h1(256)]
        cfc_mma_bf<32, 64><<<dim3(BQ / 32, (4 * H1) / 64), 128, SM1>>>(
            h0oh, h0ol, H0, H0,
            h1ih, h1il, H1,
            pW1h, pW1l, w[1][1], w[1][3], w[1][5], w[1][7],
            C1, H1, h1oh, h1ol);

        // layer 2: x = [h1_new(256) | h2(64)]
        cfc_mma_bf<32, 32><<<dim3(BQ / 32, (4 * H2) / 32), 128, SM2>>>(
            h1oh, h1ol, H1, H1,
            h2ih, h2il, H2,
            pW2h, pW2l, w[2][1], w[2][3], w[2][5], w[2][7],
            C2, H2, h2oh, h2ol);
    }

    // final motor-layer state (ping buffer 0): hi+lo -> fp32 output
    extract_out<<<(BQ * H2 + 255) / 256, 256>>>(p2h, p2l, (float*)d_out, BQ * H2);
}

// round 9
// speedup vs baseline: 2.3094x; 1.0463x over previous
#include <cuda_runtime.h>
#include <cuda_bf16.h>
#include <math.h>
#include <stdint.h>

// Problem constants
#define BQ   512   // batch
#define KT   64    // timesteps
#define EBD  256
#define VFD  512
#define SENS 768
#define H0   512
#define H1   256
#define H2   64
#define C0   1280  // 768 + 512
#define C1   768   // 512 + 256
#define C2   320   // 256 + 64

// ---------------- device scratch (static, no allocation) ----------------
__device__ __align__(16) __nv_bfloat16 Xh[(size_t)BQ * KT * SENS];
__device__ __align__(16) __nv_bfloat16 Xl[(size_t)BQ * KT * SENS];
__device__ __align__(16) __nv_bfloat16 W0h[(size_t)4 * H0 * C0];
__device__ __align__(16) __nv_bfloat16 W0l[(size_t)4 * H0 * C0];
__device__ __align__(16) __nv_bfloat16 W1h[(size_t)4 * H1 * C1];
__device__ __align__(16) __nv_bfloat16 W1l[(size_t)4 * H1 * C1];
__device__ __align__(16) __nv_bfloat16 W2h[(size_t)4 * H2 * C2];
__device__ __align__(16) __nv_bfloat16 W2l[(size_t)4 * H2 * C2];
__device__ __align__(16) __nv_bfloat16 h0h[2][BQ * H0];
__device__ __align__(16) __nv_bfloat16 h0l[2][BQ * H0];
__device__ __align__(16) __nv_bfloat16 h1h[2][BQ * H1];
__device__ __align__(16) __nv_bfloat16 h1l[2][BQ * H1];
__device__ __align__(16) __nv_bfloat16 h2h[2][BQ * H2];
__device__ __align__(16) __nv_bfloat16 h2l[2][BQ * H2];

// ---------------- helpers ----------------
__device__ __forceinline__ void bf16_split(float v, __nv_bfloat16& hi, __nv_bfloat16& lo)
{
    hi = __float2bfloat16(v);
    lo = __float2bfloat16(v - __bfloat162float(hi));
}

__device__ __forceinline__ void mma_bf16(float* d, const uint32_t* a, const uint32_t* b)
{
    asm volatile(
        "mma.sync.aligned.m16n8k16.row.col.f32.bf16.bf16.f32 "
        "{%0,%1,%2,%3}, {%4,%5,%6,%7}, {%8,%9}, {%0,%1,%2,%3};\n"
        : "+f"(d[0]), "+f"(d[1]), "+f"(d[2]), "+f"(d[3])
        : "r"(a[0]), "r"(a[1]), "r"(a[2]), "r"(a[3]),
          "r"(b[0]), "r"(b[1]));
}

__device__ __forceinline__ void cpa16(uint32_t* dst_smem, const void* src_gmem)
{
    uint32_t d = (uint32_t)__cvta_generic_to_shared(dst_smem);
    asm volatile("cp.async.cg.shared.global [%0], [%1], 16;\n" :: "r"(d), "l"(src_gmem));
}

// ---------------- prep kernels ----------------
__global__ void prep_weights_bf(const float* __restrict__ ff1, const float* __restrict__ ff2,
                                const float* __restrict__ ta,  const float* __restrict__ tb,
                                const float* __restrict__ mask,
                                __nv_bfloat16* __restrict__ dh, __nv_bfloat16* __restrict__ dl,
                                int hid, int cat)
{
    int idx = blockIdx.x * blockDim.x + threadIdx.x;
    if (idx >= hid * cat) return;
    int j = idx / cat;
    int k = idx - j * cat;
    float m = mask[idx];
    float v[4] = { ff1[idx] * m, ff2[idx] * m, ta[idx], tb[idx] };
    #pragma unroll
    for (int q = 0; q < 4; q++) {
        __nv_bfloat16 hi, lo;
        bf16_split(v[q], hi, lo);
        size_t o = (size_t)(4 * j + q) * cat + k;
        dh[o] = hi; dl[o] = lo;
    }
}

__global__ void prep_inputs_bf(const float* __restrict__ base, const float* __restrict__ vis,
                               __nv_bfloat16* __restrict__ xh, __nv_bfloat16* __restrict__ xl)
{
    size_t idx = (size_t)blockIdx.x * blockDim.x + threadIdx.x;
    if (idx >= (size_t)BQ * KT * SENS) return;
    size_t row = idx / SENS;
    int c = (int)(idx - row * SENS);
    float v = (c < EBD) ? base[row * EBD + c] : vis[row * VFD + (c - EBD)];
    __nv_bfloat16 hi, lo;
    bf16_split(v, hi, lo);
    xh[idx] = hi; xl[idx] = lo;
}

__global__ void extract_out(const __nv_bfloat16* __restrict__ hh,
                            const __nv_bfloat16* __restrict__ hl,
                            float* __restrict__ out, int n)
{
    int i = blockIdx.x * blockDim.x + threadIdx.x;
    if (i < n) out[i] = __bfloat162float(hh[i]) + __bfloat162float(hl[i]);
}

// ---------------- fused GEMM tile (3xBF16, m16n8k16) + CfC epilogue ----------------
// One BM x BN output tile of C[M, 4*hid] = X[M, cat] @ W[cat, 4*hid] (W stored
// [4*hid][cat], k contig). acc += Ahi*Bhi + Ahi*Blo + Alo*Bhi.
template<int BM, int BN>
__device__ void cfc_tile(uint32_t* sm32, int bx, int by,
                         const __nv_bfloat16* __restrict__ s0h, const __nv_bfloat16* __restrict__ s0l,
                         int st0, int len0,
                         const __nv_bfloat16* __restrict__ s1h, const __nv_bfloat16* __restrict__ s1l,
                         int st1,
                         const __nv_bfloat16* __restrict__ Wh, const __nv_bfloat16* __restrict__ Wl,
                         const float* __restrict__ bff1, const float* __restrict__ bff2,
                         const float* __restrict__ bta,  const float* __restrict__ btb,
                         int cat, int hid,
                         __nv_bfloat16* __restrict__ oh, __nv_bfloat16* __restrict__ ol)
{
    constexpr int BK  = 32;
    constexpr int TWM = BM / 2;
    constexpr int TWN = BN / 2;
    constexpr int MT  = TWM / 16;
    constexpr int NT  = TWN / 8;
    constexpr int RS  = 20;              // row stride in uint32 (40 bf16)
    constexpr int APL = BM * RS;
    constexpr int BPL = BN * RS;

    const int tid  = threadIdx.x;
    const int lane = tid & 31;
    const int wid  = tid >> 5;
    const int wm   = wid & 1;
    const int wn   = wid >> 1;
    const int g    = lane >> 2;
    const int tc   = lane & 3;

    const int rowBase = bx * BM;
    const int colBase = by * BN;
    const int l0 = len0;

    float acc[MT][NT][4];
    #pragma unroll
    for (int i = 0; i < MT; i++)
        #pragma unroll
        for (int q = 0; q < NT; q++)
            #pragma unroll
            for (int z = 0; z < 4; z++) acc[i][q][z] = 0.0f;

    auto load_tiles = [&](int k0, int buf) {
        const __nv_bfloat16 *shi, *slo; int ss, so;
        if (k0 < l0) { shi = s0h; slo = s0l; ss = st0; so = k0; }
        else         { shi = s1h; slo = s1l; ss = st1; so = k0 - l0; }
        uint32_t* Ah = sm32 + buf * APL;
        uint32_t* Al = sm32 + 2 * APL + buf * APL;
        #pragma unroll
        for (int i = 0; i < BM * 4 / 128; i++) {
            int idx = tid + i * 128;
            int r = idx >> 2, c = idx & 3;
            size_t go = (size_t)(rowBase + r) * ss + so + c * 8;
            cpa16(Ah + r * RS + c * 4, shi + go);
            cpa16(Al + r * RS + c * 4, slo + go);
        }
        uint32_t* Bh = sm32 + 4 * APL + buf * BPL;
        uint32_t* Bl = sm32 + 4 * APL + 2 * BPL + buf * BPL;
        #pragma unroll
        for (int i = 0; i < BN * 4 / 128; i++) {
            int idx = tid + i * 128;
            int r = idx >> 2, c = idx & 3;
            size_t go = (size_t)(colBase + r) * cat + k0 + c * 8;
            cpa16(Bh + r * RS + c * 4, Wh + go);
            cpa16(Bl + r * RS + c * 4, Wl + go);
        }
        asm volatile("cp.async.commit_group;\n");
    };

    load_tiles(0, 0);

    const int ntile = cat / BK;
    int buf = 0;
    for (int it = 0; it < ntile; it++, buf ^= 1) {
        if (it + 1 < ntile) {
            load_tiles((it + 1) * BK, buf ^ 1);
            asm volatile("cp.async.wait_group 1;\n");
        } else {
            asm volatile("cp.async.wait_group 0;\n");
        }
        __syncthreads();

        const uint32_t* Ah = sm32 + buf * APL;
        const uint32_t* Al = sm32 + 2 * APL + buf * APL;
        const uint32_t* Bh = sm32 + 4 * APL + buf * BPL;
        const uint32_t* Bl = sm32 + 4 * APL + 2 * BPL + buf * BPL;

        #pragma unroll
        for (int k16 = 0; k16 < 2; k16++) {
            const int kb = k16 * 8;
            uint32_t ah[MT][4], al[MT][4];
            #pragma unroll
            for (int mt = 0; mt < MT; mt++) {
                const int r0 = (wm * TWM + mt * 16 + g) * RS + kb + tc;
                ah[mt][0] = Ah[r0];
                ah[mt][1] = Ah[r0 + 8 * RS];
                ah[mt][2] = Ah[r0 + 4];
                ah[mt][3] = Ah[r0 + 8 * RS + 4];
                al[mt][0] = Al[r0];
                al[mt][1] = Al[r0 + 8 * RS];
                al[mt][2] = Al[r0 + 4];
                al[mt][3] = Al[r0 + 8 * RS + 4];
            }
            uint32_t bh[NT][2], bl[NT][2];
            #pragma unroll
            for (int nt = 0; nt < NT; nt++) {
                const int c0 = (wn * TWN + nt * 8 + g) * RS + kb + tc;
                bh[nt][0] = Bh[c0];
                bh[nt][1] = Bh[c0 + 4];
                bl[nt][0] = Bl[c0];
                bl[nt][1] = Bl[c0 + 4];
            }
            #pragma unroll
            for (int mt = 0; mt < MT; mt++)
                #pragma unroll
                for (int nt = 0; nt < NT; nt++)
                    mma_bf16(acc[mt][nt], ah[mt], bh[nt]);
            #pragma unroll
            for (int mt = 0; mt < MT; mt++)
                #pragma unroll
                for (int nt = 0; nt < NT; nt++)
                    mma_bf16(acc[mt][nt], ah[mt], bl[nt]);
            #pragma unroll
            for (int mt = 0; mt < MT; mt++)
                #pragma unroll
                for (int nt = 0; nt < NT; nt++)
                    mma_bf16(acc[mt][nt], al[mt], bh[nt]);
        }
        __syncthreads();
    }

    // ---------------- CfC epilogue ----------------
    #pragma unroll
    for (int nt = 0; nt < NT; nt++) {
        const int cb = colBase + wn * TWN + nt * 8;
        const int j  = (cb >> 2) + (tc >> 1);
        const float bf1 = bff1[j], bf2 = bff2[j], bt1 = bta[j], bt2 = btb[j];
        #pragma unroll
        for (int mt = 0; mt < MT; mt++) {
            const int r = rowBase + wm * TWM + mt * 16 + g;
            float d0 = acc[mt][nt][0], d1 = acc[mt][nt][1];
            float d2 = acc[mt][nt][2], d3 = acc[mt][nt][3];
            float o0 = __shfl_xor_sync(0xffffffffu, d0, 1);
            float o1 = __shfl_xor_sync(0xffffffffu, d1, 1);
            float o2 = __shfl_xor_sync(0xffffffffu, d2, 1);
            float o3 = __shfl_xor_sync(0xffffffffu, d3, 1);
            if (!(lane & 1)) {
                {
                    float f1 = tanhf(d0 + bf1);
                    float f2 = tanhf(d1 + bf2);
                    float s  = (o0 + bt1) + (o1 + bt2);
                    float ti = 1.0f / (1.0f + expf(-s));
                    float v  = f1 + ti * (f2 - f1);
                    __nv_bfloat16 hi, lo; bf16_split(v, hi, lo);
                    oh[(size_t)r * hid + j] = hi;
                    ol[(size_t)r * hid + j] = lo;
                }
                {
                    float f1 = tanhf(d2 + bf1);
                    float f2 = tanhf(d3 + bf2);
                    float s  = (o2 + bt1) + (o3 + bt2);
                    float ti = 1.0f / (1.0f + expf(-s));
                    float v  = f1 + ti * (f2 - f1);
                    __nv_bfloat16 hi, lo; bf16_split(v, hi, lo);
                    oh[(size_t)(r + 8) * hid + j] = hi;
                    ol[(size_t)(r + 8) * hid + j] = lo;
                }
            }
        }
    }
}

// ---------------- merged pipeline-slot kernel ----------------
// One launch per pipeline slot s: blocks [0,256) = L0(t=s),
// [256,512) = L1(t=s-1), [512,640) = L2(t=s-2). Kernel boundary = sync.
// Ping-pong slots never collide within a launch:
//   L0(s) writes h0[(s+1)&1];  L1(s-1) reads h0[s&1]
//   L1(s-1) writes h1[s&1];    L2(s-2) reads h1[(s-1)&1]
__global__ __launch_bounds__(128)
void fused_step(int s,
                const float* __restrict__ b0f1, const float* __restrict__ b0f2,
                const float* __restrict__ b0ta, const float* __restrict__ b0tb,
                const float* __restrict__ b1f1, const float* __restrict__ b1f2,
                const float* __restrict__ b1ta, const float* __restrict__ b1tb,
                const float* __restrict__ b2f1, const float* __restrict__ b2f2,
                const float* __restrict__ b2ta, const float* __restrict__ b2tb)
{
    extern __shared__ __align__(16) uint32_t sm32[];
    int b = blockIdx.x;
    if (b < 256) {
        int t = s;
        if (t >= KT) return;
        int pi = t & 1, po = pi ^ 1;
        cfc_tile<64, 64>(sm32, b & 7, b >> 3,
                         Xh + (size_t)t * SENS, Xl + (size_t)t * SENS, KT * SENS, SENS,
                         h0h[pi], h0l[pi], H0,
                         W0h, W0l, b0f1, b0f2, b0ta, b0tb,
                         C0, H0, h0h[po], h0l[po]);
    } else if (b < 512) {
        int t = s - 1;
        if (t < 0 || t >= KT) return;
        int pi = t & 1, po = pi ^ 1;
        b -= 256;
        cfc_tile<32, 64>(sm32, b & 15, b >> 4,
                         h0h[po], h0l[po], H0, H0,
                         h1h[pi], h1l[pi], H1,
                         W1h, W1l, b1f1, b1f2, b1ta, b1tb,
                         C1, H1, h1h[po], h1l[po]);
    } else {
        int t = s - 2;
        if (t < 0 || t >= KT) return;
        int pi = t & 1, po = pi ^ 1;
        b -= 512;
        cfc_tile<32, 32>(sm32, b & 15, b >> 4,
                         h1h[po], h1l[po], H1, H1,
                         h2h[pi], h2l[pi], H2,
                         W2h, W2l, b2f1, b2f2, b2ta, b2tb,
                         C2, H2, h2h[po], h2l[po]);
    }
}

// ---------------- host launcher ----------------
extern "C" void kernel_launch(void* const* d_in, const int* in_sizes, int n_in,
                              void* d_out, int out_size)
{
    const float* base = (const float*)d_in[0];
    const float* vis  = (const float*)d_in[1];
    const float* w[3][9];
    for (int li = 0; li < 3; li++)
        for (int q = 0; q < 9; q++)
            w[li][q] = (const float*)d_in[2 + li * 9 + q];

    __nv_bfloat16 *pXh, *pXl, *pW0h, *pW0l, *pW1h, *pW1l, *pW2h, *pW2l;
    __nv_bfloat16 *p0h, *p0l, *p1h, *p1l, *p2h, *p2l;
    cudaGetSymbolAddress((void**)&pXh, Xh);   cudaGetSymbolAddress((void**)&pXl, Xl);
    cudaGetSymbolAddress((void**)&pW0h, W0h); cudaGetSymbolAddress((void**)&pW0l, W0l);
    cudaGetSymbolAddress((void**)&pW1h, W1h); cudaGetSymbolAddress((void**)&pW1l, W1l);
    cudaGetSymbolAddress((void**)&pW2h, W2h); cudaGetSymbolAddress((void**)&pW2l, W2l);
    cudaGetSymbolAddress((void**)&p0h, h0h);  cudaGetSymbolAddress((void**)&p0l, h0l);
    cudaGetSymbolAddress((void**)&p1h, h1h);  cudaGetSymbolAddress((void**)&p1l, h1l);
    cudaGetSymbolAddress((void**)&p2h, h2h);  cudaGetSymbolAddress((void**)&p2l, h2l);

    // dynamic smem for the largest path (<64,64>): 4*APL+4*BPL u32 = 40960 B
    constexpr int SMF = (64 + 64) * 320;

    // zero initial hidden states (ping buffer 0)
    cudaMemsetAsync(p0h, 0, (size_t)BQ * H0 * sizeof(__nv_bfloat16));
    cudaMemsetAsync(p0l, 0, (size_t)BQ * H0 * sizeof(__nv_bfloat16));
    cudaMemsetAsync(p1h, 0, (size_t)BQ * H1 * sizeof(__nv_bfloat16));
    cudaMemsetAsync(p1l, 0, (size_t)BQ * H1 * sizeof(__nv_bfloat16));
    cudaMemsetAsync(p2h, 0, (size_t)BQ * H2 * sizeof(__nv_bfloat16));
    cudaMemsetAsync(p2l, 0, (size_t)BQ * H2 * sizeof(__nv_bfloat16));

    // prep
    {
        size_t n = (size_t)BQ * KT * SENS;
        prep_inputs_bf<<<(unsigned)((n + 255) / 256), 256>>>(base, vis, pXh, pXl);
    }
    prep_weights_bf<<<(H0 * C0 + 255) / 256, 256>>>(w[0][0], w[0][2], w[0][4], w[0][6], w[0][8], pW0h, pW0l, H0, C0);
    prep_weights_bf<<<(H1 * C1 + 255) / 256, 256>>>(w[1][0], w[1][2], w[1][4], w[1][6], w[1][8], pW1h, pW1l, H1, C1);
    prep_weights_bf<<<(H2 * C2 + 255) / 256, 256>>>(w[2][0], w[2][2], w[2][4], w[2][6], w[2][8], pW2h, pW2l, H2, C2);

    // pipeline: slot s runs L0(s) || L1(s-1) || L2(s-2)
    for (int s = 0; s < KT + 2; s++) {
        fused_step<<<640, 128, SMF>>>(s,
            w[0][1], w[0][3], w[0][5], w[0][7],
            w[1][1], w[1][3], w[1][5], w[1][7],
            w[2][1], w[2][3], w[2][5], w[2][7]);
    }

    // final motor-layer state: L2(KT-1) wrote slot (KT)&1 == 0
    extract_out<<<(BQ * H2 + 255) / 256, 256>>>(p2h, p2l, (float*)d_out, BQ * H2);
}